// round 16
// baseline (speedup 1.0000x reference)
#include <cuda_runtime.h>
#include <cstdint>
#include <cstddef>

// MeanAggregator on GB300 (sm_103a; ptxas target sm_103 -> legacy tf32 mma.sync).
//
//   out[:, 0:64]   = self_x @ Ws + bs                       (prep kernel)
//   out[:, 64:128] = (adj @ (nx @ Wn)) / max(rowsum(adj),1) + bn
//     -> tf32 GEMM split-K=2: P[h] = adj[:,h-half] @ B[:,h-half]^T,
//        B[64,16384] = (nx@Wn)^T; deg partial via FFMA on A fragments.
//        reduce: out[:,64:128] = (P0+P1)/max(deg0+deg1,1) + bn.
//
// R15 = champion GEMM + reduce verbatim; prep goes to 4 threads/row
// (65536 threads, 2x warps/SM) with a skewed weight layout
// (row n at n*68 + (n>>4)*4) making the 4 n-groups conflict-free.

#define NROWS    16384
#define KHALF    8192
#define KC       32
#define NIT      (KHALF / KC)            // 256
#define RSTRIDE  36                      // floats per smem row (32 + 4 pad)
#define A_ROWS   128
#define B_ROWS   64
#define A_ST_BYTES (A_ROWS * RSTRIDE * 4)            // 18432
#define B_ST_BYTES (B_ROWS * RSTRIDE * 4)            // 9216
#define ST_BYTES   (A_ST_BYTES + B_ST_BYTES)         // 27648
#define SMEM_TOTAL (256 + 4 * ST_BYTES)              // 110848
#define PSTRIDE  80
#define WSTRIDE  68                      // prep weight stride (16B aligned)

__device__ float g_B[(size_t)B_ROWS * NROWS];              // 4 MB
__device__ float g_P[2][(size_t)NROWS * PSTRIDE];          // 10.5 MB partials

// ---------------- helpers ----------------

static __device__ __forceinline__ uint32_t smem_u32(const void* p) {
    uint32_t a;
    asm("{ .reg .u64 t; cvta.to.shared.u64 t, %1; cvt.u32.u64 %0, t; }"
        : "=r"(a) : "l"(p));
    return a;
}

static __device__ __forceinline__ void cp16(uint32_t dst, const void* src) {
    asm volatile("cp.async.cg.shared.global [%0], [%1], 16;"
                 :: "r"(dst), "l"(src) : "memory");
}

static __device__ __forceinline__ void mma_tf32(float* d,
                                                uint32_t a0, uint32_t a1,
                                                uint32_t a2, uint32_t a3,
                                                uint32_t b0, uint32_t b1) {
    asm volatile(
        "mma.sync.aligned.m16n8k8.row.col.f32.tf32.tf32.f32 "
        "{%0,%1,%2,%3}, {%4,%5,%6,%7}, {%8,%9}, {%0,%1,%2,%3};"
        : "+f"(d[0]), "+f"(d[1]), "+f"(d[2]), "+f"(d[3])
        : "r"(a0), "r"(a1), "r"(a2), "r"(a3), "r"(b0), "r"(b1));
}

// ---------------- stage loader (A 128 rows + B 64 rows = 1536 chunks) --------

static __device__ __forceinline__ void load_stage(char* smem, int slot, int k0,
                                                  int m0, int tid,
                                                  const float* __restrict__ adj) {
    char* base = smem + 256 + slot * ST_BYTES;
#pragma unroll
    for (int i = 0; i < 12; i++) {
        const int c = i * 128 + tid;
        if (c < 1024) {
            const int row = c >> 3, w = c & 7;
            cp16(smem_u32(base + row * (RSTRIDE * 4) + w * 16),
                 adj + (size_t)(m0 + row) * NROWS + k0 + w * 4);
        } else {
            const int cb = c - 1024;            // 0..511
            const int row = cb >> 3, w = cb & 7;
            cp16(smem_u32(base + A_ST_BYTES + row * (RSTRIDE * 4) + w * 16),
                 g_B + (size_t)row * NROWS + k0 + w * 4);
        }
    }
}

// ---------------- main GEMM (split-K partial) — champion, untouched ----------

__global__ void __launch_bounds__(128, 2)
gcn_gemm(const float* __restrict__ adj) {
    extern __shared__ char smem[];
    const int tid   = threadIdx.x;
    const int lane  = tid & 31;
    const int warp  = tid >> 5;              // 0..3
    const int mw    = warp >> 1;             // m-strip 0/1 (64 rows each)
    const int nh    = warp & 1;              // n-half 0/1
    const int rm    = mw * 64;
    const int g     = lane >> 2;
    const int tig   = lane & 3;
    const int mtile = blockIdx.x >> 1;
    const int kh    = blockIdx.x & 1;
    const int m0    = mtile * 128;
    const int kbase = kh * KHALF;
    float* __restrict__ P = g_P[kh];

    load_stage(smem, 0, kbase,          m0, tid, adj);
    asm volatile("cp.async.commit_group;" ::: "memory");
    load_stage(smem, 1, kbase + KC,     m0, tid, adj);
    asm volatile("cp.async.commit_group;" ::: "memory");
    load_stage(smem, 2, kbase + 2 * KC, m0, tid, adj);
    asm volatile("cp.async.commit_group;" ::: "memory");

    float acc[4][4][4];                       // [m16 tile][n8 tile][frag]
#pragma unroll
    for (int mt = 0; mt < 4; mt++)
#pragma unroll
        for (int nt = 0; nt < 4; nt++)
#pragma unroll
            for (int q = 0; q < 4; q++) acc[mt][nt][q] = 0.0f;
    float dg[8];                               // deg partials rows mt*16+{g,g+8}
#pragma unroll
    for (int r = 0; r < 8; r++) dg[r] = 0.0f;

    for (int it = 0; it < NIT; it++) {
        asm volatile("cp.async.wait_group 2;" ::: "memory");
        __syncthreads();

        const int ld = it + 3;
        if (ld < NIT) load_stage(smem, ld & 3, kbase + ld * KC, m0, tid, adj);
        asm volatile("cp.async.commit_group;" ::: "memory");

        const uint32_t* base = (const uint32_t*)(smem + 256 + (it & 3) * ST_BYTES);
        const uint32_t* Ap = base + (rm + g) * RSTRIDE + tig;
        const uint32_t* Bp = base + A_ROWS * RSTRIDE + g * RSTRIDE + tig * 8;

        // B fragments: 8 x LDS.128 (fragment-ordered rows, 4 n-tiles)
        uint4 Br[4][2];
#pragma unroll
        for (int t = 0; t < 4; t++) {
            const int tr = (nh * 32 + t * 8) * RSTRIDE;
            Br[t][0] = *reinterpret_cast<const uint4*>(Bp + tr);
            Br[t][1] = *reinterpret_cast<const uint4*>(Bp + tr + 4);
        }

        // A fragments (4 m16 tiles), register double-buffered across kk
        uint32_t a[16], an[16];
#pragma unroll
        for (int mt = 0; mt < 4; mt++) {
            a[mt * 4 + 0] = Ap[(mt * 16) * RSTRIDE];
            a[mt * 4 + 1] = Ap[(mt * 16 + 8) * RSTRIDE];
            a[mt * 4 + 2] = Ap[(mt * 16) * RSTRIDE + 4];
            a[mt * 4 + 3] = Ap[(mt * 16 + 8) * RSTRIDE + 4];
        }
#pragma unroll
        for (int kk = 0; kk < 4; kk++) {
            if (kk < 3) {
                const int ko = (kk + 1) * 8;
#pragma unroll
                for (int mt = 0; mt < 4; mt++) {
                    an[mt * 4 + 0] = Ap[ko + (mt * 16) * RSTRIDE];
                    an[mt * 4 + 1] = Ap[ko + (mt * 16 + 8) * RSTRIDE];
                    an[mt * 4 + 2] = Ap[ko + (mt * 16) * RSTRIDE + 4];
                    an[mt * 4 + 3] = Ap[ko + (mt * 16 + 8) * RSTRIDE + 4];
                }
            }
#pragma unroll
            for (int mt = 0; mt < 4; mt++) {
                dg[mt * 2 + 0] += __uint_as_float(a[mt * 4 + 0])
                                + __uint_as_float(a[mt * 4 + 2]);
                dg[mt * 2 + 1] += __uint_as_float(a[mt * 4 + 1])
                                + __uint_as_float(a[mt * 4 + 3]);
            }
            const int h = kk >> 1;
            const int q = (kk & 1) * 2;
#pragma unroll
            for (int nt = 0; nt < 4; nt++) {
                const uint32_t* bp = reinterpret_cast<const uint32_t*>(&Br[nt][h]);
#pragma unroll
                for (int mt = 0; mt < 4; mt++)
                    mma_tf32(acc[mt][nt], a[mt * 4 + 0], a[mt * 4 + 1],
                             a[mt * 4 + 2], a[mt * 4 + 3], bp[q], bp[q + 1]);
            }
#pragma unroll
            for (int j = 0; j < 16; j++) a[j] = an[j];
        }
    }

    // ---- write partials (cols 0..63) + deg partial (col 64) ----
#pragma unroll
    for (int r = 0; r < 8; r++) {
        dg[r] += __shfl_xor_sync(0xffffffffu, dg[r], 1);
        dg[r] += __shfl_xor_sync(0xffffffffu, dg[r], 2);
    }
#pragma unroll
    for (int mt = 0; mt < 4; mt++) {
        const int r0 = m0 + rm + mt * 16 + g;
        float* p0 = P + (size_t)r0 * PSTRIDE;
        float* p1 = P + (size_t)(r0 + 8) * PSTRIDE;
#pragma unroll
        for (int nt = 0; nt < 4; nt++) {
            const int dcol = nh * 32 + nt * 8 + tig * 2;
            *reinterpret_cast<float2*>(p0 + dcol) =
                make_float2(acc[mt][nt][0], acc[mt][nt][1]);
            *reinterpret_cast<float2*>(p1 + dcol) =
                make_float2(acc[mt][nt][2], acc[mt][nt][3]);
        }
        if (nh == 0 && tig == 0) {
            p0[64] = dg[mt * 2 + 0];
            p1[64] = dg[mt * 2 + 1];
        }
    }
}

// ---------------- reduce: combine K-halves, deg divide, bias ----------------

__global__ void __launch_bounds__(256)
gcn_reduce(const float* __restrict__ bn, float* __restrict__ out) {
    __shared__ float sb[64];
    const int tid = threadIdx.x;
    if (tid < 64) sb[tid] = bn[tid];
    __syncthreads();

    const int t   = blockIdx.x * 256 + tid;  // 65536 threads
    const int row = t >> 2;
    const int q   = t & 3;
    const float* p0 = g_P[0] + (size_t)row * PSTRIDE;
    const float* p1 = g_P[1] + (size_t)row * PSTRIDE;
    const float inv = 1.0f / fmaxf(p0[64] + p1[64], 1.0f);
    float* op = out + (size_t)row * 128 + 64 + q * 16;
#pragma unroll
    for (int j = 0; j < 4; j++) {
        const int c = q * 16 + j * 4;
        const float4 a = *reinterpret_cast<const float4*>(p0 + c);
        const float4 b = *reinterpret_cast<const float4*>(p1 + c);
        float4 v;
        v.x = (a.x + b.x) * inv + sb[c];
        v.y = (a.y + b.y) * inv + sb[c + 1];
        v.z = (a.z + b.z) * inv + sb[c + 2];
        v.w = (a.w + b.w) * inv + sb[c + 3];
        *reinterpret_cast<float4*>(op + j * 4) = v;
    }
}

// ---------------- prep: out_self + fragment-ordered B ----------------
// 256 blocks x 256 thr, 64 rows/block, 4 thr/row (16 dots each).
// Weight row n stored at n*WSTRIDE + (n>>4)*4: the 4 n-groups in an
// LDS.128 phase land 4 banks apart -> conflict-free.

static __device__ __forceinline__ float to_tf32(float x) {
    uint32_t t;
    asm("cvt.rna.tf32.f32 %0, %1;" : "=r"(t) : "f"(x));
    return __uint_as_float(t);
}

static __device__ __forceinline__ int wskew(int n) {
    return n * WSTRIDE + (n >> 4) * 4;
}

__global__ void __launch_bounds__(256)
gcn_prep(const float* __restrict__ sx, const float* __restrict__ nx,
         const float* __restrict__ Ws, const float* __restrict__ Wn,
         const float* __restrict__ bs, float* __restrict__ out) {
    __shared__ float wsT[64 * WSTRIDE + 16];
    __shared__ float wnT[64 * WSTRIDE + 16];
    __shared__ float sbias[64];
    const int tid = threadIdx.x;
    for (int i = tid; i < 4096; i += 256) {
        const int d = i >> 6, n = i & 63;
        wsT[wskew(n) + d] = Ws[i];
        wnT[wskew(n) + d] = Wn[i];
    }
    if (tid < 64) sbias[tid] = bs[tid];
    __syncthreads();

    const int m  = blockIdx.x * 64 + (tid >> 2);   // 64 rows/block, 4 thr/row
    const int n0 = (tid & 3) * 16;
    const int wb = wskew(n0);                       // group base (j<16 same skew)
    const int c  = m & 31;
    const size_t col = (size_t)(m & ~31) + (c & 3) * 8 + (c >> 2);  // frag order
    {
        float4 x[16];
        const float4* xp = reinterpret_cast<const float4*>(sx + (size_t)m * 64);
#pragma unroll
        for (int i = 0; i < 16; i++) x[i] = xp[i];
        float ob[16];
#pragma unroll
        for (int j = 0; j < 16; j += 2) {           // paired dots: 8 FMA chains
            const float4* w0 = reinterpret_cast<const float4*>(wsT + wb + j * WSTRIDE);
            const float4* w1 = reinterpret_cast<const float4*>(wsT + wb + (j + 1) * WSTRIDE);
            float4 s0 = make_float4(0.f, 0.f, 0.f, 0.f);
            float4 s1 = make_float4(0.f, 0.f, 0.f, 0.f);
#pragma unroll
            for (int i = 0; i < 16; i++) {
                const float4 a = w0[i], b = w1[i];
                s0.x = fmaf(x[i].x, a.x, s0.x); s0.y = fmaf(x[i].y, a.y, s0.y);
                s0.z = fmaf(x[i].z, a.z, s0.z); s0.w = fmaf(x[i].w, a.w, s0.w);
                s1.x = fmaf(x[i].x, b.x, s1.x); s1.y = fmaf(x[i].y, b.y, s1.y);
                s1.z = fmaf(x[i].z, b.z, s1.z); s1.w = fmaf(x[i].w, b.w, s1.w);
            }
            ob[j]     = (s0.x + s0.y) + (s0.z + s0.w) + sbias[n0 + j];
            ob[j + 1] = (s1.x + s1.y) + (s1.z + s1.w) + sbias[n0 + j + 1];
        }
        float4* op = reinterpret_cast<float4*>(out + (size_t)m * 128 + n0);
#pragma unroll
        for (int j = 0; j < 4; j++)
            op[j] = make_float4(ob[j * 4], ob[j * 4 + 1],
                                ob[j * 4 + 2], ob[j * 4 + 3]);
    }
    {
        float4 x[16];
        const float4* xp = reinterpret_cast<const float4*>(nx + (size_t)m * 64);
#pragma unroll
        for (int i = 0; i < 16; i++) x[i] = xp[i];
#pragma unroll
        for (int j = 0; j < 16; j += 2) {
            const float4* w0 = reinterpret_cast<const float4*>(wnT + wb + j * WSTRIDE);
            const float4* w1 = reinterpret_cast<const float4*>(wnT + wb + (j + 1) * WSTRIDE);
            float4 s0 = make_float4(0.f, 0.f, 0.f, 0.f);
            float4 s1 = make_float4(0.f, 0.f, 0.f, 0.f);
#pragma unroll
            for (int i = 0; i < 16; i++) {
                const float4 a = w0[i], b = w1[i];
                s0.x = fmaf(x[i].x, a.x, s0.x); s0.y = fmaf(x[i].y, a.y, s0.y);
                s0.z = fmaf(x[i].z, a.z, s0.z); s0.w = fmaf(x[i].w, a.w, s0.w);
                s1.x = fmaf(x[i].x, b.x, s1.x); s1.y = fmaf(x[i].y, b.y, s1.y);
                s1.z = fmaf(x[i].z, b.z, s1.z); s1.w = fmaf(x[i].w, b.w, s1.w);
            }
            g_B[(size_t)(n0 + j) * NROWS + col] =
                to_tf32((s0.x + s0.y) + (s0.z + s0.w));
            g_B[(size_t)(n0 + j + 1) * NROWS + col] =
                to_tf32((s1.x + s1.y) + (s1.z + s1.w));
        }
    }
}

// ---------------- launch ----------------

extern "C" void kernel_launch(void* const* d_in, const int* in_sizes, int n_in,
                              void* d_out, int out_size) {
    const float* sx  = (const float*)d_in[0];
    const float* nx  = (const float*)d_in[1];
    const float* adj = (const float*)d_in[2];
    const float* Ws  = (const float*)d_in[3];
    const float* Wn  = (const float*)d_in[4];
    const float* bs  = (const float*)d_in[5];
    const float* bn  = (const float*)d_in[6];
    float* out = (float*)d_out;

    cudaFuncSetAttribute(gcn_gemm, cudaFuncAttributeMaxDynamicSharedMemorySize,
                         SMEM_TOTAL);
    gcn_prep<<<NROWS / 64, 256>>>(sx, nx, Ws, Wn, bs, out);
    gcn_gemm<<<2 * (NROWS / 128), 128, SMEM_TOTAL>>>(adj);
    gcn_reduce<<<NROWS / 64, 256>>>(bn, out);
}

// round 17
// speedup vs baseline: 1.0202x; 1.0202x over previous
#include <cuda_runtime.h>
#include <cstdint>
#include <cstddef>

// MeanAggregator on GB300 (sm_103a; ptxas target sm_103 -> legacy tf32 mma.sync).
//
//   out[:, 0:64]   = self_x @ Ws + bs                       (prep kernel)
//   out[:, 64:128] = (adj @ (nx @ Wn)) / max(rowsum(adj),1) + bn
//     -> tf32 GEMM split-K=2: P[h] = adj[:,h-half] @ B[:,h-half]^T,
//        B[64,16384] = (nx@Wn)^T; deg partial via FFMA on A fragments.
//        reduce: out[:,64:128] = (P0+P1)/max(deg0+deg1,1) + bn.
//
// R16 = champion GEMM + reduce verbatim; prep register-blocks 2 m-rows per
// thread (halves smem weight-read volume, the measured bound), k-chunked.

#define NROWS    16384
#define KHALF    8192
#define KC       32
#define NIT      (KHALF / KC)            // 256
#define RSTRIDE  36                      // floats per smem row (32 + 4 pad)
#define A_ROWS   128
#define B_ROWS   64
#define A_ST_BYTES (A_ROWS * RSTRIDE * 4)            // 18432
#define B_ST_BYTES (B_ROWS * RSTRIDE * 4)            // 9216
#define ST_BYTES   (A_ST_BYTES + B_ST_BYTES)         // 27648
#define SMEM_TOTAL (256 + 4 * ST_BYTES)              // 110848
#define PSTRIDE  80
#define WSTRIDE  68                      // prep weight stride (16B aligned)

__device__ float g_B[(size_t)B_ROWS * NROWS];              // 4 MB
__device__ float g_P[2][(size_t)NROWS * PSTRIDE];          // 10.5 MB partials

// ---------------- helpers ----------------

static __device__ __forceinline__ uint32_t smem_u32(const void* p) {
    uint32_t a;
    asm("{ .reg .u64 t; cvta.to.shared.u64 t, %1; cvt.u32.u64 %0, t; }"
        : "=r"(a) : "l"(p));
    return a;
}

static __device__ __forceinline__ void cp16(uint32_t dst, const void* src) {
    asm volatile("cp.async.cg.shared.global [%0], [%1], 16;"
                 :: "r"(dst), "l"(src) : "memory");
}

static __device__ __forceinline__ void mma_tf32(float* d,
                                                uint32_t a0, uint32_t a1,
                                                uint32_t a2, uint32_t a3,
                                                uint32_t b0, uint32_t b1) {
    asm volatile(
        "mma.sync.aligned.m16n8k8.row.col.f32.tf32.tf32.f32 "
        "{%0,%1,%2,%3}, {%4,%5,%6,%7}, {%8,%9}, {%0,%1,%2,%3};"
        : "+f"(d[0]), "+f"(d[1]), "+f"(d[2]), "+f"(d[3])
        : "r"(a0), "r"(a1), "r"(a2), "r"(a3), "r"(b0), "r"(b1));
}

// ---------------- stage loader (A 128 rows + B 64 rows = 1536 chunks) --------

static __device__ __forceinline__ void load_stage(char* smem, int slot, int k0,
                                                  int m0, int tid,
                                                  const float* __restrict__ adj) {
    char* base = smem + 256 + slot * ST_BYTES;
#pragma unroll
    for (int i = 0; i < 12; i++) {
        const int c = i * 128 + tid;
        if (c < 1024) {
            const int row = c >> 3, w = c & 7;
            cp16(smem_u32(base + row * (RSTRIDE * 4) + w * 16),
                 adj + (size_t)(m0 + row) * NROWS + k0 + w * 4);
        } else {
            const int cb = c - 1024;            // 0..511
            const int row = cb >> 3, w = cb & 7;
            cp16(smem_u32(base + A_ST_BYTES + row * (RSTRIDE * 4) + w * 16),
                 g_B + (size_t)row * NROWS + k0 + w * 4);
        }
    }
}

// ---------------- main GEMM (split-K partial) — champion, untouched ----------

__global__ void __launch_bounds__(128, 2)
gcn_gemm(const float* __restrict__ adj) {
    extern __shared__ char smem[];
    const int tid   = threadIdx.x;
    const int lane  = tid & 31;
    const int warp  = tid >> 5;              // 0..3
    const int mw    = warp >> 1;             // m-strip 0/1 (64 rows each)
    const int nh    = warp & 1;              // n-half 0/1
    const int rm    = mw * 64;
    const int g     = lane >> 2;
    const int tig   = lane & 3;
    const int mtile = blockIdx.x >> 1;
    const int kh    = blockIdx.x & 1;
    const int m0    = mtile * 128;
    const int kbase = kh * KHALF;
    float* __restrict__ P = g_P[kh];

    load_stage(smem, 0, kbase,          m0, tid, adj);
    asm volatile("cp.async.commit_group;" ::: "memory");
    load_stage(smem, 1, kbase + KC,     m0, tid, adj);
    asm volatile("cp.async.commit_group;" ::: "memory");
    load_stage(smem, 2, kbase + 2 * KC, m0, tid, adj);
    asm volatile("cp.async.commit_group;" ::: "memory");

    float acc[4][4][4];                       // [m16 tile][n8 tile][frag]
#pragma unroll
    for (int mt = 0; mt < 4; mt++)
#pragma unroll
        for (int nt = 0; nt < 4; nt++)
#pragma unroll
            for (int q = 0; q < 4; q++) acc[mt][nt][q] = 0.0f;
    float dg[8];                               // deg partials rows mt*16+{g,g+8}
#pragma unroll
    for (int r = 0; r < 8; r++) dg[r] = 0.0f;

    for (int it = 0; it < NIT; it++) {
        asm volatile("cp.async.wait_group 2;" ::: "memory");
        __syncthreads();

        const int ld = it + 3;
        if (ld < NIT) load_stage(smem, ld & 3, kbase + ld * KC, m0, tid, adj);
        asm volatile("cp.async.commit_group;" ::: "memory");

        const uint32_t* base = (const uint32_t*)(smem + 256 + (it & 3) * ST_BYTES);
        const uint32_t* Ap = base + (rm + g) * RSTRIDE + tig;
        const uint32_t* Bp = base + A_ROWS * RSTRIDE + g * RSTRIDE + tig * 8;

        // B fragments: 8 x LDS.128 (fragment-ordered rows, 4 n-tiles)
        uint4 Br[4][2];
#pragma unroll
        for (int t = 0; t < 4; t++) {
            const int tr = (nh * 32 + t * 8) * RSTRIDE;
            Br[t][0] = *reinterpret_cast<const uint4*>(Bp + tr);
            Br[t][1] = *reinterpret_cast<const uint4*>(Bp + tr + 4);
        }

        // A fragments (4 m16 tiles), register double-buffered across kk
        uint32_t a[16], an[16];
#pragma unroll
        for (int mt = 0; mt < 4; mt++) {
            a[mt * 4 + 0] = Ap[(mt * 16) * RSTRIDE];
            a[mt * 4 + 1] = Ap[(mt * 16 + 8) * RSTRIDE];
            a[mt * 4 + 2] = Ap[(mt * 16) * RSTRIDE + 4];
            a[mt * 4 + 3] = Ap[(mt * 16 + 8) * RSTRIDE + 4];
        }
#pragma unroll
        for (int kk = 0; kk < 4; kk++) {
            if (kk < 3) {
                const int ko = (kk + 1) * 8;
#pragma unroll
                for (int mt = 0; mt < 4; mt++) {
                    an[mt * 4 + 0] = Ap[ko + (mt * 16) * RSTRIDE];
                    an[mt * 4 + 1] = Ap[ko + (mt * 16 + 8) * RSTRIDE];
                    an[mt * 4 + 2] = Ap[ko + (mt * 16) * RSTRIDE + 4];
                    an[mt * 4 + 3] = Ap[ko + (mt * 16 + 8) * RSTRIDE + 4];
                }
            }
#pragma unroll
            for (int mt = 0; mt < 4; mt++) {
                dg[mt * 2 + 0] += __uint_as_float(a[mt * 4 + 0])
                                + __uint_as_float(a[mt * 4 + 2]);
                dg[mt * 2 + 1] += __uint_as_float(a[mt * 4 + 1])
                                + __uint_as_float(a[mt * 4 + 3]);
            }
            const int h = kk >> 1;
            const int q = (kk & 1) * 2;
#pragma unroll
            for (int nt = 0; nt < 4; nt++) {
                const uint32_t* bp = reinterpret_cast<const uint32_t*>(&Br[nt][h]);
#pragma unroll
                for (int mt = 0; mt < 4; mt++)
                    mma_tf32(acc[mt][nt], a[mt * 4 + 0], a[mt * 4 + 1],
                             a[mt * 4 + 2], a[mt * 4 + 3], bp[q], bp[q + 1]);
            }
#pragma unroll
            for (int j = 0; j < 16; j++) a[j] = an[j];
        }
    }

    // ---- write partials (cols 0..63) + deg partial (col 64) ----
#pragma unroll
    for (int r = 0; r < 8; r++) {
        dg[r] += __shfl_xor_sync(0xffffffffu, dg[r], 1);
        dg[r] += __shfl_xor_sync(0xffffffffu, dg[r], 2);
    }
#pragma unroll
    for (int mt = 0; mt < 4; mt++) {
        const int r0 = m0 + rm + mt * 16 + g;
        float* p0 = P + (size_t)r0 * PSTRIDE;
        float* p1 = P + (size_t)(r0 + 8) * PSTRIDE;
#pragma unroll
        for (int nt = 0; nt < 4; nt++) {
            const int dcol = nh * 32 + nt * 8 + tig * 2;
            *reinterpret_cast<float2*>(p0 + dcol) =
                make_float2(acc[mt][nt][0], acc[mt][nt][1]);
            *reinterpret_cast<float2*>(p1 + dcol) =
                make_float2(acc[mt][nt][2], acc[mt][nt][3]);
        }
        if (nh == 0 && tig == 0) {
            p0[64] = dg[mt * 2 + 0];
            p1[64] = dg[mt * 2 + 1];
        }
    }
}

// ---------------- reduce: combine K-halves, deg divide, bias ----------------

__global__ void __launch_bounds__(256)
gcn_reduce(const float* __restrict__ bn, float* __restrict__ out) {
    __shared__ float sb[64];
    const int tid = threadIdx.x;
    if (tid < 64) sb[tid] = bn[tid];
    __syncthreads();

    const int t   = blockIdx.x * 256 + tid;  // 65536 threads
    const int row = t >> 2;
    const int q   = t & 3;
    const float* p0 = g_P[0] + (size_t)row * PSTRIDE;
    const float* p1 = g_P[1] + (size_t)row * PSTRIDE;
    const float inv = 1.0f / fmaxf(p0[64] + p1[64], 1.0f);
    float* op = out + (size_t)row * 128 + 64 + q * 16;
#pragma unroll
    for (int j = 0; j < 4; j++) {
        const int c = q * 16 + j * 4;
        const float4 a = *reinterpret_cast<const float4*>(p0 + c);
        const float4 b = *reinterpret_cast<const float4*>(p1 + c);
        float4 v;
        v.x = (a.x + b.x) * inv + sb[c];
        v.y = (a.y + b.y) * inv + sb[c + 1];
        v.z = (a.z + b.z) * inv + sb[c + 2];
        v.w = (a.w + b.w) * inv + sb[c + 3];
        *reinterpret_cast<float4*>(op + j * 4) = v;
    }
}

// ---------------- prep: out_self + fragment-ordered B ----------------
// 128 blocks x 256 thr. Each thread: 2 m-rows x 16 n-cols (weight reads
// amortized over 2 rows -> smem volume halved). k-chunked (4 x 16 floats).
// Skewed weight layout (row n at n*68 + (n>>4)*4): conflict-free.

static __device__ __forceinline__ float to_tf32(float x) {
    uint32_t t;
    asm("cvt.rna.tf32.f32 %0, %1;" : "=r"(t) : "f"(x));
    return __uint_as_float(t);
}

static __device__ __forceinline__ int wskew(int n) {
    return n * WSTRIDE + (n >> 4) * 4;
}

// Computes a 2x16 block of X @ W^T(rows n0..n0+15); W in skewed smem.
static __device__ __forceinline__ void block2x16(
    const float* __restrict__ x0g, const float* __restrict__ x1g,
    const float* __restrict__ wT, int wb, float* __restrict__ acc /*[32]*/) {
#pragma unroll
    for (int i = 0; i < 32; i++) acc[i] = 0.0f;
#pragma unroll
    for (int kc = 0; kc < 4; kc++) {
        float4 x0[4], x1[4];
#pragma unroll
        for (int i = 0; i < 4; i++) {
            x0[i] = reinterpret_cast<const float4*>(x0g)[kc * 4 + i];
            x1[i] = reinterpret_cast<const float4*>(x1g)[kc * 4 + i];
        }
#pragma unroll
        for (int j = 0; j < 16; j++) {
            const float4* w = reinterpret_cast<const float4*>(
                wT + wb + j * WSTRIDE + kc * 16);
            float4 s0 = make_float4(0.f, 0.f, 0.f, 0.f);
            float4 s1 = make_float4(0.f, 0.f, 0.f, 0.f);
#pragma unroll
            for (int i = 0; i < 4; i++) {
                const float4 wv = w[i];
                s0.x = fmaf(x0[i].x, wv.x, s0.x);
                s0.y = fmaf(x0[i].y, wv.y, s0.y);
                s0.z = fmaf(x0[i].z, wv.z, s0.z);
                s0.w = fmaf(x0[i].w, wv.w, s0.w);
                s1.x = fmaf(x1[i].x, wv.x, s1.x);
                s1.y = fmaf(x1[i].y, wv.y, s1.y);
                s1.z = fmaf(x1[i].z, wv.z, s1.z);
                s1.w = fmaf(x1[i].w, wv.w, s1.w);
            }
            acc[j]      += (s0.x + s0.y) + (s0.z + s0.w);
            acc[16 + j] += (s1.x + s1.y) + (s1.z + s1.w);
        }
    }
}

__global__ void __launch_bounds__(256)
gcn_prep(const float* __restrict__ sx, const float* __restrict__ nx,
         const float* __restrict__ Ws, const float* __restrict__ Wn,
         const float* __restrict__ bs, float* __restrict__ out) {
    __shared__ float wsT[64 * WSTRIDE + 16];
    __shared__ float wnT[64 * WSTRIDE + 16];
    __shared__ float sbias[64];
    const int tid = threadIdx.x;
    for (int i = tid; i < 4096; i += 256) {
        const int d = i >> 6, n = i & 63;
        wsT[wskew(n) + d] = Ws[i];
        wnT[wskew(n) + d] = Wn[i];
    }
    if (tid < 64) sbias[tid] = bs[tid];
    __syncthreads();

    const int mp = blockIdx.x * 128 + (tid >> 2) * 2;   // rows mp, mp+1
    const int n0 = (tid & 3) * 16;
    const int wb = wskew(n0);
    // fragment-ordered g_B columns for both rows
    const int c0 = mp & 31, c1 = (mp + 1) & 31;
    const size_t col0 = (size_t)(mp & ~31) + (c0 & 3) * 8 + (c0 >> 2);
    const size_t col1 = (size_t)((mp + 1) & ~31) + (c1 & 3) * 8 + (c1 >> 2);

    float acc[32];
    {   // out_self
        block2x16(sx + (size_t)mp * 64, sx + (size_t)(mp + 1) * 64, wsT, wb, acc);
        float4* o0 = reinterpret_cast<float4*>(out + (size_t)mp * 128 + n0);
        float4* o1 = reinterpret_cast<float4*>(out + (size_t)(mp + 1) * 128 + n0);
#pragma unroll
        for (int j = 0; j < 4; j++) {
            o0[j] = make_float4(acc[j * 4]      + sbias[n0 + j * 4],
                                acc[j * 4 + 1]  + sbias[n0 + j * 4 + 1],
                                acc[j * 4 + 2]  + sbias[n0 + j * 4 + 2],
                                acc[j * 4 + 3]  + sbias[n0 + j * 4 + 3]);
            o1[j] = make_float4(acc[16 + j * 4]     + sbias[n0 + j * 4],
                                acc[16 + j * 4 + 1] + sbias[n0 + j * 4 + 1],
                                acc[16 + j * 4 + 2] + sbias[n0 + j * 4 + 2],
                                acc[16 + j * 4 + 3] + sbias[n0 + j * 4 + 3]);
        }
    }
    {   // B = (nx@Wn)^T, fragment-ordered
        block2x16(nx + (size_t)mp * 64, nx + (size_t)(mp + 1) * 64, wnT, wb, acc);
#pragma unroll
        for (int j = 0; j < 16; j++) {
            g_B[(size_t)(n0 + j) * NROWS + col0] = to_tf32(acc[j]);
            g_B[(size_t)(n0 + j) * NROWS + col1] = to_tf32(acc[16 + j]);
        }
    }
}

// ---------------- launch ----------------

extern "C" void kernel_launch(void* const* d_in, const int* in_sizes, int n_in,
                              void* d_out, int out_size) {
    const float* sx  = (const float*)d_in[0];
    const float* nx  = (const float*)d_in[1];
    const float* adj = (const float*)d_in[2];
    const float* Ws  = (const float*)d_in[3];
    const float* Wn  = (const float*)d_in[4];
    const float* bs  = (const float*)d_in[5];
    const float* bn  = (const float*)d_in[6];
    float* out = (float*)d_out;

    cudaFuncSetAttribute(gcn_gemm, cudaFuncAttributeMaxDynamicSharedMemorySize,
                         SMEM_TOTAL);
    gcn_prep<<<NROWS / 128, 256>>>(sx, nx, Ws, Wn, bs, out);
    gcn_gemm<<<2 * (NROWS / 128), 128, SMEM_TOTAL>>>(adj);
    gcn_reduce<<<NROWS / 64, 256>>>(bn, out);
}